// round 14
// baseline (speedup 1.0000x reference)
#include <cuda_runtime.h>
#include <cuda_fp16.h>
#include <cstdint>

#define K_DIM 4096
#define KP    (K_DIM / 4)
#define M_DIM 8192
#define N_DIM 16384

#define BM 128
#define BN 256
#define KTILES (K_DIM / 64)                  // 64
#define NSTAGES 3
#define A_STAGE_BYTES (BM * 128)             // 16384
#define B_STAGE_BYTES (BN * 128)             // 32768
#define STAGE_BYTES (A_STAGE_BYTES + B_STAGE_BYTES)    // 49152
#define SMEM_TOTAL (NSTAGES * STAGE_BYTES)             // 147456

#define NT0 5                                 // gemm0 N-tiles (256-wide): ~2.2 waves
#define W_ROWS0 (NT0 * BN)                    // 1280 W rows for chunk0
#define ABS_BLOCKS 2368

__device__ __forceinline__ uint32_t smem_u32(const void* p) {
    uint32_t a;
    asm("{ .reg .u64 t; cvta.to.shared.u64 t, %1; cvt.u32.u64 %0, t; }" : "=r"(a) : "l"(p));
    return a;
}

#define CP_ASYNC16(dst, src) \
    asm volatile("cp.async.cg.shared.global [%0], [%1], 16;" :: "r"(dst), "l"(src))
#define CP_COMMIT() asm volatile("cp.async.commit_group;")
#define CP_WAIT(n)  asm volatile("cp.async.wait_group %0;" :: "n"(n))

#define LDSM4(r0, r1, r2, r3, addr) \
    asm volatile("ldmatrix.sync.aligned.m8n8.x4.shared.b16 {%0,%1,%2,%3}, [%4];" \
                 : "=r"(r0), "=r"(r1), "=r"(r2), "=r"(r3) : "r"(addr))

__device__ __forceinline__ void mma_f16(float* c, const int* a, const int* b) {
    asm volatile(
        "mma.sync.aligned.m16n8k16.row.col.f32.f16.f16.f32 "
        "{%0,%1,%2,%3}, {%4,%5,%6,%7}, {%8,%9}, {%0,%1,%2,%3};"
        : "+f"(c[0]), "+f"(c[1]), "+f"(c[2]), "+f"(c[3])
        : "r"(a[0]), "r"(a[1]), "r"(a[2]), "r"(a[3]), "r"(b[0]), "r"(b[1]));
}

// ---------------- device scratch ----------------
__device__ float g_alpha;
__device__ float g_part[ABS_BLOCKS];
__device__ float g_gamma[M_DIM];
__device__ uint2 g_wh[N_DIM * KP];   // 128 MB: W as f16 ternary
__device__ uint2 g_xh[M_DIM * KP];   // 64 MB: x as f16 ints <= 127

// ---------------- kernel 1: partial sums of |W|, 4 MLP chains ----------------
__global__ void k_abs_partial(const float4* __restrict__ w4) {
    __shared__ float sh[256];
    const int total4 = N_DIM * KP;
    const int stride = gridDim.x * blockDim.x;
    float s0 = 0.f, s1 = 0.f, s2 = 0.f, s3 = 0.f;
    int i = blockIdx.x * blockDim.x + threadIdx.x;
    for (; i + 3 * stride < total4; i += 4 * stride) {
        float4 v0 = w4[i];
        float4 v1 = w4[i + stride];
        float4 v2 = w4[i + 2 * stride];
        float4 v3 = w4[i + 3 * stride];
        s0 += fabsf(v0.x) + fabsf(v0.y) + fabsf(v0.z) + fabsf(v0.w);
        s1 += fabsf(v1.x) + fabsf(v1.y) + fabsf(v1.z) + fabsf(v1.w);
        s2 += fabsf(v2.x) + fabsf(v2.y) + fabsf(v2.z) + fabsf(v2.w);
        s3 += fabsf(v3.x) + fabsf(v3.y) + fabsf(v3.z) + fabsf(v3.w);
    }
    for (; i < total4; i += stride) {
        float4 v = w4[i];
        s0 += fabsf(v.x) + fabsf(v.y) + fabsf(v.z) + fabsf(v.w);
    }
    sh[threadIdx.x] = (s0 + s1) + (s2 + s3);
    __syncthreads();
    for (int o = 128; o > 0; o >>= 1) {
        if (threadIdx.x < o) sh[threadIdx.x] += sh[threadIdx.x + o];
        __syncthreads();
    }
    if (threadIdx.x == 0) g_part[blockIdx.x] = sh[0];
}

// ---------------- kernel 2: finalize alpha ----------------
__global__ void k_alpha_final() {
    __shared__ float sh[256];
    float s = 0.f;
    for (int i = threadIdx.x; i < ABS_BLOCKS; i += 256) s += g_part[i];
    sh[threadIdx.x] = s;
    __syncthreads();
    for (int o = 128; o > 0; o >>= 1) {
        if (threadIdx.x < o) sh[threadIdx.x] += sh[threadIdx.x + o];
        __syncthreads();
    }
    if (threadIdx.x == 0)
        g_alpha = sh[0] / (float)((long long)N_DIM * K_DIM) + 1e-8f;
}

// ---------------- quant helpers ----------------
__device__ __forceinline__ uint32_t pack_h2(float a, float b) {
    __half2 h = __floats2half2_rn(a, b);
    return *reinterpret_cast<uint32_t*>(&h);
}
__device__ __forceinline__ uint2 quant_pack_h(float4 v, float s, float lo, float hi) {
    float q0 = fmaxf(lo, fminf(hi, rintf(v.x * s)));
    float q1 = fmaxf(lo, fminf(hi, rintf(v.y * s)));
    float q2 = fmaxf(lo, fminf(hi, rintf(v.z * s)));
    float q3 = fmaxf(lo, fminf(hi, rintf(v.w * s)));
    uint2 r;
    r.x = pack_h2(q0, q1);
    r.y = pack_h2(q2, q3);
    return r;
}

// ---------------- kernel 3: quantize weight chunk -> f16 ternary ----------------
__global__ void k_quant_w(const float4* __restrict__ w4, int start4, int count4) {
    const float inv = 1.0f / g_alpha;
    const int stride = gridDim.x * blockDim.x;
    int i = blockIdx.x * blockDim.x + threadIdx.x;
    for (; i + stride < count4; i += 2 * stride) {
        g_wh[start4 + i]          = quant_pack_h(w4[start4 + i], inv, -1.f, 1.f);
        g_wh[start4 + i + stride] = quant_pack_h(w4[start4 + i + stride], inv, -1.f, 1.f);
    }
    if (i < count4)
        g_wh[start4 + i] = quant_pack_h(w4[start4 + i], inv, -1.f, 1.f);
}

// ---------------- kernel 4: per-row activation quant -> f16 ints ----------------
__global__ void k_quant_x(const float4* __restrict__ x4) {
    __shared__ float sh[256];
    __shared__ float s_gamma;
    const int row = blockIdx.x;
    const float4* xr = x4 + (size_t)row * KP;
    float m = 0.f;
    float4 v[4];
    #pragma unroll
    for (int t = 0; t < 4; t++) {
        v[t] = xr[threadIdx.x + t * 256];
        m = fmaxf(m, fmaxf(fmaxf(fabsf(v[t].x), fabsf(v[t].y)),
                           fmaxf(fabsf(v[t].z), fabsf(v[t].w))));
    }
    sh[threadIdx.x] = m;
    __syncthreads();
    for (int o = 128; o > 0; o >>= 1) {
        if (threadIdx.x < o) sh[threadIdx.x] = fmaxf(sh[threadIdx.x], sh[threadIdx.x + o]);
        __syncthreads();
    }
    if (threadIdx.x == 0) {
        float g = fmaxf(sh[0], 1e-8f);
        s_gamma = g;
        g_gamma[row] = g;
    }
    __syncthreads();
    const float s = 127.0f / s_gamma;
    #pragma unroll
    for (int t = 0; t < 4; t++) {
        g_xh[(size_t)row * KP + threadIdx.x + t * 256] =
            quant_pack_h(v[t], s, -127.f, 127.f);
    }
}

// ---------------- kernel 5: f16 mma GEMM, 128x256 tile, 64x64 warps, ldmatrix ----------------
__device__ __forceinline__ void load_stage(uint32_t stageBase, int kt,
                                           int rowBase, int colBase, int tid) {
    const char* gx = (const char*)g_xh;
    const char* gw = (const char*)g_wh;
    const uint32_t aBase = stageBase;
    const uint32_t bBase = stageBase + A_STAGE_BYTES;
    // A: 128 rows x 8 chunks = 1024 (4 per thread)
    #pragma unroll
    for (int t = 0; t < 4; t++) {
        int q = tid + t * 256;
        int r = q >> 3, c = q & 7;
        const char* src = gx + (((size_t)(rowBase + r)) << 13) + (kt << 7) + (c << 4);
        uint32_t dst = aBase + (uint32_t)(r * 128 + ((c ^ (r & 7)) << 4));
        CP_ASYNC16(dst, src);
    }
    // B: 256 rows x 8 chunks = 2048 (8 per thread)
    #pragma unroll
    for (int t = 0; t < 8; t++) {
        int q = tid + t * 256;
        int r = q >> 3, c = q & 7;
        const char* src = gw + (((size_t)(colBase + r)) << 13) + (kt << 7) + (c << 4);
        uint32_t dst = bBase + (uint32_t)(r * 128 + ((c ^ (r & 7)) << 4));
        CP_ASYNC16(dst, src);
    }
}

__global__ __launch_bounds__(256, 1) void k_gemm_mma(float* __restrict__ out, int colOff) {
    extern __shared__ __align__(1024) char smem[];
    const uint32_t sbase = smem_u32(smem);
    const int tid = threadIdx.x;
    const int wid = tid >> 5;
    const int l   = tid & 31;
    const int warp_m = wid & 1;        // 0..1 -> 64-row halves of 128
    const int warp_n = wid >> 1;       // 0..3 -> 64-col quarters of 256
    const int rowBase = blockIdx.y * BM;
    const int colBase = (blockIdx.x + colOff) * BN;

    // ldmatrix per-lane address components
    const int aRow = warp_m * 64 + (l & 7) + ((l >> 3) & 1) * 8;   // + mt*16
    const int aHi  = (l >> 4) & 1;
    const int bRow = warp_n * 64 + ((l >> 4) & 1) * 8 + (l & 7);   // + p*16
    const int bHi  = (l >> 3) & 1;
    const int lsw  = l & 7;

    float acc[4][8][4];
    #pragma unroll
    for (int mt = 0; mt < 4; mt++)
        #pragma unroll
        for (int nt = 0; nt < 8; nt++)
            #pragma unroll
            for (int r = 0; r < 4; r++) acc[mt][nt][r] = 0.f;

    load_stage(sbase + 0 * STAGE_BYTES, 0, rowBase, colBase, tid);
    CP_COMMIT();
    load_stage(sbase + 1 * STAGE_BYTES, 1, rowBase, colBase, tid);
    CP_COMMIT();

    int stage = 0;
    for (int kt = 0; kt < KTILES; kt++) {
        CP_WAIT(1);
        __syncthreads();

        if (kt + 2 < KTILES) {
            int ts = stage + 2; if (ts >= NSTAGES) ts -= NSTAGES;
            load_stage(sbase + ts * STAGE_BYTES, kt + 2, rowBase, colBase, tid);
        }
        CP_COMMIT();

        const uint32_t aBase = sbase + stage * STAGE_BYTES;
        const uint32_t bBase = aBase + A_STAGE_BYTES;
        const uint32_t aLane = aBase + (uint32_t)(aRow * 128);
        const uint32_t bLane = bBase + (uint32_t)(bRow * 128);

        #pragma unroll
        for (int ks = 0; ks < 4; ks++) {
            int a[4][4], b[8][2];
            const uint32_t aChunk = (uint32_t)(((ks * 2 + aHi) ^ lsw) << 4);
            const uint32_t bChunk = (uint32_t)(((ks * 2 + bHi) ^ lsw) << 4);
            #pragma unroll
            for (int mt = 0; mt < 4; mt++) {
                LDSM4(a[mt][0], a[mt][1], a[mt][2], a[mt][3],
                      aLane + (uint32_t)(mt * 2048) + aChunk);
            }
            #pragma unroll
            for (int p = 0; p < 4; p++) {
                LDSM4(b[2 * p][0], b[2 * p][1], b[2 * p + 1][0], b[2 * p + 1][1],
                      bLane + (uint32_t)(p * 2048) + bChunk);
            }
            #pragma unroll
            for (int mt = 0; mt < 4; mt++)
                #pragma unroll
                for (int nt = 0; nt < 8; nt++)
                    mma_f16(acc[mt][nt], a[mt], b[nt]);
        }
        stage++; if (stage >= NSTAGES) stage = 0;
    }

    // epilogue
    const float gscale = g_alpha * (1.0f / 127.0f);
    #pragma unroll
    for (int mt = 0; mt < 4; mt++) {
        const int m0 = rowBase + warp_m * 64 + mt * 16 + (l >> 2);
        const float s0 = g_gamma[m0] * gscale;
        const float s1 = g_gamma[m0 + 8] * gscale;
        #pragma unroll
        for (int nt = 0; nt < 8; nt++) {
            const int cbase = colBase + warp_n * 64 + nt * 8 + ((l & 3) << 1);
            float2 o0, o1;
            o0.x = acc[mt][nt][0] * s0;
            o0.y = acc[mt][nt][1] * s0;
            o1.x = acc[mt][nt][2] * s1;
            o1.y = acc[mt][nt][3] * s1;
            *(float2*)(out + (size_t)m0 * N_DIM + cbase) = o0;
            *(float2*)(out + (size_t)(m0 + 8) * N_DIM + cbase) = o1;
        }
    }
}

// ---------------- launch: overlap quant_w(rest) with gemm0 ----------------
extern "C" void kernel_launch(void* const* d_in, const int* in_sizes, int n_in,
                              void* d_out, int out_size) {
    const float4* x4 = (const float4*)d_in[0];
    const float4* w4 = (const float4*)d_in[1];
    float* out = (float*)d_out;

    static bool init_done = false;
    static cudaStream_t s2;
    static cudaEvent_t evStart, evX, evW0, evW;
    if (!init_done) {
        cudaFuncSetAttribute(k_gemm_mma, cudaFuncAttributeMaxDynamicSharedMemorySize,
                             SMEM_TOTAL);
        cudaStreamCreateWithFlags(&s2, cudaStreamNonBlocking);
        cudaEventCreateWithFlags(&evStart, cudaEventDisableTiming);
        cudaEventCreateWithFlags(&evX, cudaEventDisableTiming);
        cudaEventCreateWithFlags(&evW0, cudaEventDisableTiming);
        cudaEventCreateWithFlags(&evW, cudaEventDisableTiming);
        init_done = true;
    }

    const int C0 = W_ROWS0 * KP;
    const int CR = (N_DIM - W_ROWS0) * KP;

    cudaEventRecord(evStart, 0);
    cudaStreamWaitEvent(s2, evStart, 0);
    k_quant_x<<<M_DIM, 256, 0, s2>>>(x4);
    cudaEventRecord(evX, s2);

    k_abs_partial<<<ABS_BLOCKS, 256>>>(w4);
    k_alpha_final<<<1, 256>>>();

    k_quant_w<<<1280, 256>>>(w4, 0, C0);
    cudaEventRecord(evW0, 0);

    cudaStreamWaitEvent(s2, evW0, 0);
    k_quant_w<<<4096, 256, 0, s2>>>(w4, C0, CR);
    cudaEventRecord(evW, s2);

    cudaStreamWaitEvent(0, evX, 0);
    {
        dim3 grid0(NT0, M_DIM / BM);
        k_gemm_mma<<<grid0, 256, SMEM_TOTAL>>>(out, 0);
    }

    cudaStreamWaitEvent(0, evW, 0);
    {
        dim3 grid1((N_DIM / BN) - NT0, M_DIM / BM);
        k_gemm_mma<<<grid1, 256, SMEM_TOTAL>>>(out, NT0);
    }
}

// round 15
// speedup vs baseline: 1.1684x; 1.1684x over previous
#include <cuda_runtime.h>
#include <cuda_fp16.h>
#include <cstdint>

#define K_DIM 4096
#define KP    (K_DIM / 4)
#define M_DIM 8192
#define N_DIM 16384

#define BM 128
#define BN 128
#define KTILES (K_DIM / 64)                  // 64
#define NSTAGES 3
#define A_STAGE_BYTES (BM * 128)             // 16384
#define B_STAGE_BYTES (BN * 128)             // 16384
#define STAGE_BYTES (A_STAGE_BYTES + B_STAGE_BYTES)    // 32768
#define SMEM_TOTAL (NSTAGES * STAGE_BYTES)             // 98304

#define NT0 19                                // gemm0 N-tiles: 1216 CTAs = 4 waves
#define W_ROWS0 (NT0 * BN)                    // 2432 W rows for chunk0
#define ABS_BLOCKS 2368

__device__ __forceinline__ uint32_t smem_u32(const void* p) {
    uint32_t a;
    asm("{ .reg .u64 t; cvta.to.shared.u64 t, %1; cvt.u32.u64 %0, t; }" : "=r"(a) : "l"(p));
    return a;
}

#define CP_ASYNC16(dst, src) \
    asm volatile("cp.async.cg.shared.global [%0], [%1], 16;" :: "r"(dst), "l"(src))
#define CP_COMMIT() asm volatile("cp.async.commit_group;")
#define CP_WAIT(n)  asm volatile("cp.async.wait_group %0;" :: "n"(n))

#define LDSM4(r0, r1, r2, r3, addr) \
    asm volatile("ldmatrix.sync.aligned.m8n8.x4.shared.b16 {%0,%1,%2,%3}, [%4];" \
                 : "=r"(r0), "=r"(r1), "=r"(r2), "=r"(r3) : "r"(addr))

__device__ __forceinline__ void mma_f16(float* c, const int* a, const int* b) {
    asm volatile(
        "mma.sync.aligned.m16n8k16.row.col.f32.f16.f16.f32 "
        "{%0,%1,%2,%3}, {%4,%5,%6,%7}, {%8,%9}, {%0,%1,%2,%3};"
        : "+f"(c[0]), "+f"(c[1]), "+f"(c[2]), "+f"(c[3])
        : "r"(a[0]), "r"(a[1]), "r"(a[2]), "r"(a[3]), "r"(b[0]), "r"(b[1]));
}

// ---------------- device scratch ----------------
__device__ float g_alpha;
__device__ float g_part[ABS_BLOCKS];
__device__ float g_gamma[M_DIM];
__device__ uint2 g_wh[N_DIM * KP];   // 128 MB: W as f16 ternary
__device__ uint2 g_xh[M_DIM * KP];   // 64 MB: x as f16 ints <= 127

// ---------------- kernel 1: partial sums of |W|, 4 MLP chains ----------------
__global__ void k_abs_partial(const float4* __restrict__ w4) {
    __shared__ float sh[256];
    const int total4 = N_DIM * KP;
    const int stride = gridDim.x * blockDim.x;
    float s0 = 0.f, s1 = 0.f, s2 = 0.f, s3 = 0.f;
    int i = blockIdx.x * blockDim.x + threadIdx.x;
    for (; i + 3 * stride < total4; i += 4 * stride) {
        float4 v0 = w4[i];
        float4 v1 = w4[i + stride];
        float4 v2 = w4[i + 2 * stride];
        float4 v3 = w4[i + 3 * stride];
        s0 += fabsf(v0.x) + fabsf(v0.y) + fabsf(v0.z) + fabsf(v0.w);
        s1 += fabsf(v1.x) + fabsf(v1.y) + fabsf(v1.z) + fabsf(v1.w);
        s2 += fabsf(v2.x) + fabsf(v2.y) + fabsf(v2.z) + fabsf(v2.w);
        s3 += fabsf(v3.x) + fabsf(v3.y) + fabsf(v3.z) + fabsf(v3.w);
    }
    for (; i < total4; i += stride) {
        float4 v = w4[i];
        s0 += fabsf(v.x) + fabsf(v.y) + fabsf(v.z) + fabsf(v.w);
    }
    sh[threadIdx.x] = (s0 + s1) + (s2 + s3);
    __syncthreads();
    for (int o = 128; o > 0; o >>= 1) {
        if (threadIdx.x < o) sh[threadIdx.x] += sh[threadIdx.x + o];
        __syncthreads();
    }
    if (threadIdx.x == 0) g_part[blockIdx.x] = sh[0];
}

// ---------------- kernel 2: finalize alpha ----------------
__global__ void k_alpha_final() {
    __shared__ float sh[256];
    float s = 0.f;
    for (int i = threadIdx.x; i < ABS_BLOCKS; i += 256) s += g_part[i];
    sh[threadIdx.x] = s;
    __syncthreads();
    for (int o = 128; o > 0; o >>= 1) {
        if (threadIdx.x < o) sh[threadIdx.x] += sh[threadIdx.x + o];
        __syncthreads();
    }
    if (threadIdx.x == 0)
        g_alpha = sh[0] / (float)((long long)N_DIM * K_DIM) + 1e-8f;
}

// ---------------- quant helpers ----------------
__device__ __forceinline__ uint32_t pack_h2(float a, float b) {
    __half2 h = __floats2half2_rn(a, b);
    return *reinterpret_cast<uint32_t*>(&h);
}
__device__ __forceinline__ uint2 quant_pack_h(float4 v, float s, float lo, float hi) {
    float q0 = fmaxf(lo, fminf(hi, rintf(v.x * s)));
    float q1 = fmaxf(lo, fminf(hi, rintf(v.y * s)));
    float q2 = fmaxf(lo, fminf(hi, rintf(v.z * s)));
    float q3 = fmaxf(lo, fminf(hi, rintf(v.w * s)));
    uint2 r;
    r.x = pack_h2(q0, q1);
    r.y = pack_h2(q2, q3);
    return r;
}

// ---------------- kernel 3: quantize weight chunk -> f16 ternary ----------------
__global__ void k_quant_w(const float4* __restrict__ w4, int start4, int count4) {
    const float inv = 1.0f / g_alpha;
    const int stride = gridDim.x * blockDim.x;
    int i = blockIdx.x * blockDim.x + threadIdx.x;
    for (; i + stride < count4; i += 2 * stride) {
        g_wh[start4 + i]          = quant_pack_h(w4[start4 + i], inv, -1.f, 1.f);
        g_wh[start4 + i + stride] = quant_pack_h(w4[start4 + i + stride], inv, -1.f, 1.f);
    }
    if (i < count4)
        g_wh[start4 + i] = quant_pack_h(w4[start4 + i], inv, -1.f, 1.f);
}

// ---------------- kernel 4: per-row activation quant -> f16 ints ----------------
__global__ void k_quant_x(const float4* __restrict__ x4) {
    __shared__ float sh[256];
    __shared__ float s_gamma;
    const int row = blockIdx.x;
    const float4* xr = x4 + (size_t)row * KP;
    float m = 0.f;
    float4 v[4];
    #pragma unroll
    for (int t = 0; t < 4; t++) {
        v[t] = xr[threadIdx.x + t * 256];
        m = fmaxf(m, fmaxf(fmaxf(fabsf(v[t].x), fabsf(v[t].y)),
                           fmaxf(fabsf(v[t].z), fabsf(v[t].w))));
    }
    sh[threadIdx.x] = m;
    __syncthreads();
    for (int o = 128; o > 0; o >>= 1) {
        if (threadIdx.x < o) sh[threadIdx.x] = fmaxf(sh[threadIdx.x], sh[threadIdx.x + o]);
        __syncthreads();
    }
    if (threadIdx.x == 0) {
        float g = fmaxf(sh[0], 1e-8f);
        s_gamma = g;
        g_gamma[row] = g;
    }
    __syncthreads();
    const float s = 127.0f / s_gamma;
    #pragma unroll
    for (int t = 0; t < 4; t++) {
        g_xh[(size_t)row * KP + threadIdx.x + t * 256] =
            quant_pack_h(v[t], s, -127.f, 127.f);
    }
}

// ---------------- kernel 5: f16 mma.sync GEMM, stage-specialized ----------------
__device__ __forceinline__ void load_stage(uint32_t stageBase, int kt,
                                           int rowBase, int colBase, int tid) {
    const char* gx = (const char*)g_xh;
    const char* gw = (const char*)g_wh;
    const uint32_t aBase = stageBase;
    const uint32_t bBase = stageBase + A_STAGE_BYTES;
    #pragma unroll
    for (int t = 0; t < 4; t++) {
        int q = tid + t * 256;
        int r = q >> 3, c = q & 7;
        const char* src = gx + (((size_t)(rowBase + r)) << 13) + (kt << 7) + (c << 4);
        uint32_t dst = aBase + (uint32_t)(r * 128 + ((c ^ (r & 7)) << 4));
        CP_ASYNC16(dst, src);
    }
    #pragma unroll
    for (int t = 0; t < 4; t++) {
        int q = tid + t * 256;
        int r = q >> 3, c = q & 7;
        const char* src = gw + (((size_t)(colBase + r)) << 13) + (kt << 7) + (c << 4);
        uint32_t dst = bBase + (uint32_t)(r * 128 + ((c ^ (r & 7)) << 4));
        CP_ASYNC16(dst, src);
    }
}

__global__ __launch_bounds__(256, 2) void k_gemm_mma(float* __restrict__ out, int colOff) {
    extern __shared__ __align__(1024) char smem[];
    const uint32_t sbase = smem_u32(smem);
    const int tid = threadIdx.x;
    const int wid = tid >> 5;
    const int l   = tid & 31;
    const int warp_m = wid & 1;
    const int warp_n = wid >> 1;
    const int rowBase = blockIdx.y * BM;
    const int colBase = (blockIdx.x + colOff) * BN;

    const int aRow = warp_m * 64 + (l & 7) + ((l >> 3) & 1) * 8;
    const int aHi  = (l >> 4) & 1;
    const int bRow = warp_n * 32 + ((l >> 4) & 1) * 8 + (l & 7);
    const int bHi  = (l >> 3) & 1;
    const int lsw  = l & 7;

    // per-stage lane bases, computed once (compile-time stage offsets)
    const uint32_t aLaneS[NSTAGES] = {
        sbase + 0 * STAGE_BYTES + (uint32_t)(aRow * 128),
        sbase + 1 * STAGE_BYTES + (uint32_t)(aRow * 128),
        sbase + 2 * STAGE_BYTES + (uint32_t)(aRow * 128)
    };
    const uint32_t bLaneS[NSTAGES] = {
        sbase + 0 * STAGE_BYTES + A_STAGE_BYTES + (uint32_t)(bRow * 128),
        sbase + 1 * STAGE_BYTES + A_STAGE_BYTES + (uint32_t)(bRow * 128),
        sbase + 2 * STAGE_BYTES + A_STAGE_BYTES + (uint32_t)(bRow * 128)
    };

    float acc[4][4][4];
    #pragma unroll
    for (int mt = 0; mt < 4; mt++)
        #pragma unroll
        for (int nt = 0; nt < 4; nt++)
            #pragma unroll
            for (int r = 0; r < 4; r++) acc[mt][nt][r] = 0.f;

    load_stage(sbase + 0 * STAGE_BYTES, 0, rowBase, colBase, tid);
    CP_COMMIT();
    load_stage(sbase + 1 * STAGE_BYTES, 1, rowBase, colBase, tid);
    CP_COMMIT();

    int kt = 0;

    // one mainloop iteration with STG a compile-time stage literal
    #define GEMM_ITER(STG)                                                        \
    do {                                                                          \
        CP_WAIT(1);                                                               \
        __syncthreads();                                                          \
        if (kt + 2 < KTILES) {                                                    \
            load_stage(sbase + (((STG) + 2) % NSTAGES) * STAGE_BYTES, kt + 2,     \
                       rowBase, colBase, tid);                                    \
        }                                                                         \
        CP_COMMIT();                                                              \
        {                                                                         \
            const uint32_t aLane = aLaneS[(STG)];                                 \
            const uint32_t bLane = bLaneS[(STG)];                                 \
            _Pragma("unroll")                                                     \
            for (int ks = 0; ks < 4; ks++) {                                      \
                int a[4][4], b[4][2];                                             \
                const uint32_t aChunk = (uint32_t)(((ks * 2 + aHi) ^ lsw) << 4);  \
                const uint32_t bChunk = (uint32_t)(((ks * 2 + bHi) ^ lsw) << 4);  \
                _Pragma("unroll")                                                 \
                for (int mt = 0; mt < 4; mt++) {                                  \
                    LDSM4(a[mt][0], a[mt][1], a[mt][2], a[mt][3],                 \
                          aLane + (uint32_t)(mt * 2048) + aChunk);                \
                }                                                                 \
                _Pragma("unroll")                                                 \
                for (int p = 0; p < 2; p++) {                                     \
                    LDSM4(b[2 * p][0], b[2 * p][1], b[2 * p + 1][0],              \
                          b[2 * p + 1][1],                                        \
                          bLane + (uint32_t)(p * 2048) + bChunk);                 \
                }                                                                 \
                _Pragma("unroll")                                                 \
                for (int mt = 0; mt < 4; mt++)                                    \
                    _Pragma("unroll")                                             \
                    for (int nt = 0; nt < 4; nt++)                                \
                        mma_f16(acc[mt][nt], a[mt], b[nt]);                       \
            }                                                                     \
        }                                                                         \
        kt++;                                                                     \
    } while (0)

    #pragma unroll 1
    for (int grp = 0; grp < KTILES / NSTAGES; grp++) {   // 21 groups of 3
        GEMM_ITER(0);
        GEMM_ITER(1);
        GEMM_ITER(2);
    }
    GEMM_ITER(0);   // kt = 63 (64 = 21*3 + 1)

    #undef GEMM_ITER

    const float gscale = g_alpha * (1.0f / 127.0f);
    #pragma unroll
    for (int mt = 0; mt < 4; mt++) {
        const int m0 = rowBase + warp_m * 64 + mt * 16 + (l >> 2);
        const float s0 = g_gamma[m0] * gscale;
        const float s1 = g_gamma[m0 + 8] * gscale;
        #pragma unroll
        for (int nt = 0; nt < 4; nt++) {
            const int cbase = colBase + warp_n * 32 + nt * 8 + ((l & 3) << 1);
            float2 o0, o1;
            o0.x = acc[mt][nt][0] * s0;
            o0.y = acc[mt][nt][1] * s0;
            o1.x = acc[mt][nt][2] * s1;
            o1.y = acc[mt][nt][3] * s1;
            *(float2*)(out + (size_t)m0 * N_DIM + cbase) = o0;
            *(float2*)(out + (size_t)(m0 + 8) * N_DIM + cbase) = o1;
        }
    }
}

// ---------------- launch: overlap quant_w(rest) with gemm0 ----------------
extern "C" void kernel_launch(void* const* d_in, const int* in_sizes, int n_in,
                              void* d_out, int out_size) {
    const float4* x4 = (const float4*)d_in[0];
    const float4* w4 = (const float4*)d_in[1];
    float* out = (float*)d_out;

    static bool init_done = false;
    static cudaStream_t s2;
    static cudaEvent_t evStart, evX, evW0, evW;
    if (!init_done) {
        cudaFuncSetAttribute(k_gemm_mma, cudaFuncAttributeMaxDynamicSharedMemorySize,
                             SMEM_TOTAL);
        cudaStreamCreateWithFlags(&s2, cudaStreamNonBlocking);
        cudaEventCreateWithFlags(&evStart, cudaEventDisableTiming);
        cudaEventCreateWithFlags(&evX, cudaEventDisableTiming);
        cudaEventCreateWithFlags(&evW0, cudaEventDisableTiming);
        cudaEventCreateWithFlags(&evW, cudaEventDisableTiming);
        init_done = true;
    }

    const int C0 = W_ROWS0 * KP;
    const int CR = (N_DIM - W_ROWS0) * KP;

    cudaEventRecord(evStart, 0);
    cudaStreamWaitEvent(s2, evStart, 0);
    k_quant_x<<<M_DIM, 256, 0, s2>>>(x4);
    cudaEventRecord(evX, s2);

    k_abs_partial<<<ABS_BLOCKS, 256>>>(w4);
    k_alpha_final<<<1, 256>>>();

    k_quant_w<<<1824, 256>>>(w4, 0, C0);
    cudaEventRecord(evW0, 0);

    cudaStreamWaitEvent(s2, evW0, 0);
    k_quant_w<<<4096, 256, 0, s2>>>(w4, C0, CR);
    cudaEventRecord(evW, s2);

    cudaStreamWaitEvent(0, evX, 0);
    {
        dim3 grid0(NT0, M_DIM / BM);
        k_gemm_mma<<<grid0, 256, SMEM_TOTAL>>>(out, 0);
    }

    cudaStreamWaitEvent(0, evW, 0);
    {
        dim3 grid1((N_DIM / BN) - NT0, M_DIM / BM);
        k_gemm_mma<<<grid1, 256, SMEM_TOTAL>>>(out, NT0);
    }
}

// round 17
// speedup vs baseline: 1.1696x; 1.0010x over previous
#include <cuda_runtime.h>
#include <cuda_fp16.h>
#include <cstdint>

#define K_DIM 4096
#define KP    (K_DIM / 4)
#define M_DIM 8192
#define N_DIM 16384

#define BM 128
#define BN 128
#define N_TILES (N_DIM / BN)                 // 128
#define KTILES (K_DIM / 64)                  // 64
#define NSTAGES 3
#define A_STAGE_BYTES (BM * 128)             // 16384
#define B_STAGE_BYTES (BN * 128)             // 16384
#define STAGE_BYTES (A_STAGE_BYTES + B_STAGE_BYTES)    // 32768
#define SMEM_TOTAL (NSTAGES * STAGE_BYTES)             // 98304

#define NT0 19                                // gemm0 N-tiles: 1216 CTAs = 4 waves (304/wave)
#define W_ROWS0 (NT0 * BN)                    // 2432 W rows for chunk0 (HIGH rows)
#define COL_OFF0 (N_TILES - NT0)              // 109: gemm0 covers high N-tiles
#define ABS_BLOCKS 2368

__device__ __forceinline__ uint32_t smem_u32(const void* p) {
    uint32_t a;
    asm("{ .reg .u64 t; cvta.to.shared.u64 t, %1; cvt.u32.u64 %0, t; }" : "=r"(a) : "l"(p));
    return a;
}

#define CP_ASYNC16(dst, src) \
    asm volatile("cp.async.cg.shared.global [%0], [%1], 16;" :: "r"(dst), "l"(src))
#define CP_COMMIT() asm volatile("cp.async.commit_group;")
#define CP_WAIT(n)  asm volatile("cp.async.wait_group %0;" :: "n"(n))

#define LDSM4(r0, r1, r2, r3, addr) \
    asm volatile("ldmatrix.sync.aligned.m8n8.x4.shared.b16 {%0,%1,%2,%3}, [%4];" \
                 : "=r"(r0), "=r"(r1), "=r"(r2), "=r"(r3) : "r"(addr))

__device__ __forceinline__ void mma_f16(float* c, const int* a, const int* b) {
    asm volatile(
        "mma.sync.aligned.m16n8k16.row.col.f32.f16.f16.f32 "
        "{%0,%1,%2,%3}, {%4,%5,%6,%7}, {%8,%9}, {%0,%1,%2,%3};"
        : "+f"(c[0]), "+f"(c[1]), "+f"(c[2]), "+f"(c[3])
        : "r"(a[0]), "r"(a[1]), "r"(a[2]), "r"(a[3]), "r"(b[0]), "r"(b[1]));
}

// ---------------- device scratch ----------------
__device__ float g_alpha;
__device__ float g_part[ABS_BLOCKS];
__device__ float g_gamma[M_DIM];
__device__ uint2 g_wh[N_DIM * KP];   // 128 MB: W as f16 ternary
__device__ uint2 g_xh[M_DIM * KP];   // 64 MB: x as f16 ints <= 127

// ---------------- kernel 1: partial sums of |W|, 4 MLP chains ----------------
// grid-stride low->high: the HIGH tail of W is L2-resident at completion.
__global__ void k_abs_partial(const float4* __restrict__ w4) {
    __shared__ float sh[256];
    const int total4 = N_DIM * KP;
    const int stride = gridDim.x * blockDim.x;
    float s0 = 0.f, s1 = 0.f, s2 = 0.f, s3 = 0.f;
    int i = blockIdx.x * blockDim.x + threadIdx.x;
    for (; i + 3 * stride < total4; i += 4 * stride) {
        float4 v0 = w4[i];
        float4 v1 = w4[i + stride];
        float4 v2 = w4[i + 2 * stride];
        float4 v3 = w4[i + 3 * stride];
        s0 += fabsf(v0.x) + fabsf(v0.y) + fabsf(v0.z) + fabsf(v0.w);
        s1 += fabsf(v1.x) + fabsf(v1.y) + fabsf(v1.z) + fabsf(v1.w);
        s2 += fabsf(v2.x) + fabsf(v2.y) + fabsf(v2.z) + fabsf(v2.w);
        s3 += fabsf(v3.x) + fabsf(v3.y) + fabsf(v3.z) + fabsf(v3.w);
    }
    for (; i < total4; i += stride) {
        float4 v = w4[i];
        s0 += fabsf(v.x) + fabsf(v.y) + fabsf(v.z) + fabsf(v.w);
    }
    sh[threadIdx.x] = (s0 + s1) + (s2 + s3);
    __syncthreads();
    for (int o = 128; o > 0; o >>= 1) {
        if (threadIdx.x < o) sh[threadIdx.x] += sh[threadIdx.x + o];
        __syncthreads();
    }
    if (threadIdx.x == 0) g_part[blockIdx.x] = sh[0];
}

// ---------------- kernel 2: finalize alpha ----------------
__global__ void k_alpha_final() {
    __shared__ float sh[256];
    float s = 0.f;
    for (int i = threadIdx.x; i < ABS_BLOCKS; i += 256) s += g_part[i];
    sh[threadIdx.x] = s;
    __syncthreads();
    for (int o = 128; o > 0; o >>= 1) {
        if (threadIdx.x < o) sh[threadIdx.x] += sh[threadIdx.x + o];
        __syncthreads();
    }
    if (threadIdx.x == 0)
        g_alpha = sh[0] / (float)((long long)N_DIM * K_DIM) + 1e-8f;
}

// ---------------- quant helpers ----------------
__device__ __forceinline__ uint32_t pack_h2(float a, float b) {
    __half2 h = __floats2half2_rn(a, b);
    return *reinterpret_cast<uint32_t*>(&h);
}
__device__ __forceinline__ uint2 quant_pack_h(float4 v, float s, float lo, float hi) {
    float q0 = fmaxf(lo, fminf(hi, rintf(v.x * s)));
    float q1 = fmaxf(lo, fminf(hi, rintf(v.y * s)));
    float q2 = fmaxf(lo, fminf(hi, rintf(v.z * s)));
    float q3 = fmaxf(lo, fminf(hi, rintf(v.w * s)));
    uint2 r;
    r.x = pack_h2(q0, q1);
    r.y = pack_h2(q2, q3);
    return r;
}

// ---------------- kernel 3: quantize weight chunk -> f16 ternary ----------------
__global__ void k_quant_w(const float4* __restrict__ w4, int start4, int count4) {
    const float inv = 1.0f / g_alpha;
    const int stride = gridDim.x * blockDim.x;
    int i = blockIdx.x * blockDim.x + threadIdx.x;
    for (; i + stride < count4; i += 2 * stride) {
        g_wh[start4 + i]          = quant_pack_h(w4[start4 + i], inv, -1.f, 1.f);
        g_wh[start4 + i + stride] = quant_pack_h(w4[start4 + i + stride], inv, -1.f, 1.f);
    }
    if (i < count4)
        g_wh[start4 + i] = quant_pack_h(w4[start4 + i], inv, -1.f, 1.f);
}

// ---------------- kernel 4: per-row activation quant -> f16 ints ----------------
__global__ void k_quant_x(const float4* __restrict__ x4) {
    __shared__ float sh[256];
    __shared__ float s_gamma;
    const int row = blockIdx.x;
    const float4* xr = x4 + (size_t)row * KP;
    float m = 0.f;
    float4 v[4];
    #pragma unroll
    for (int t = 0; t < 4; t++) {
        v[t] = xr[threadIdx.x + t * 256];
        m = fmaxf(m, fmaxf(fmaxf(fabsf(v[t].x), fabsf(v[t].y)),
                           fmaxf(fabsf(v[t].z), fabsf(v[t].w))));
    }
    sh[threadIdx.x] = m;
    __syncthreads();
    for (int o = 128; o > 0; o >>= 1) {
        if (threadIdx.x < o) sh[threadIdx.x] = fmaxf(sh[threadIdx.x], sh[threadIdx.x + o]);
        __syncthreads();
    }
    if (threadIdx.x == 0) {
        float g = fmaxf(sh[0], 1e-8f);
        s_gamma = g;
        g_gamma[row] = g;
    }
    __syncthreads();
    const float s = 127.0f / s_gamma;
    #pragma unroll
    for (int t = 0; t < 4; t++) {
        g_xh[(size_t)row * KP + threadIdx.x + t * 256] =
            quant_pack_h(v[t], s, -127.f, 127.f);
    }
}

// ---------------- kernel 5: f16 mma.sync GEMM, stage-specialized ----------------
__device__ __forceinline__ void load_stage(uint32_t stageBase, int kt,
                                           int rowBase, int colBase, int tid) {
    const char* gx = (const char*)g_xh;
    const char* gw = (const char*)g_wh;
    const uint32_t aBase = stageBase;
    const uint32_t bBase = stageBase + A_STAGE_BYTES;
    #pragma unroll
    for (int t = 0; t < 4; t++) {
        int q = tid + t * 256;
        int r = q >> 3, c = q & 7;
        const char* src = gx + (((size_t)(rowBase + r)) << 13) + (kt << 7) + (c << 4);
        uint32_t dst = aBase + (uint32_t)(r * 128 + ((c ^ (r & 7)) << 4));
        CP_ASYNC16(dst, src);
    }
    #pragma unroll
    for (int t = 0; t < 4; t++) {
        int q = tid + t * 256;
        int r = q >> 3, c = q & 7;
        const char* src = gw + (((size_t)(colBase + r)) << 13) + (kt << 7) + (c << 4);
        uint32_t dst = bBase + (uint32_t)(r * 128 + ((c ^ (r & 7)) << 4));
        CP_ASYNC16(dst, src);
    }
}

__global__ __launch_bounds__(256, 2) void k_gemm_mma(float* __restrict__ out, int colOff) {
    extern __shared__ __align__(1024) char smem[];
    const uint32_t sbase = smem_u32(smem);
    const int tid = threadIdx.x;
    const int wid = tid >> 5;
    const int l   = tid & 31;
    const int warp_m = wid & 1;
    const int warp_n = wid >> 1;
    const int rowBase = blockIdx.y * BM;
    const int colBase = (blockIdx.x + colOff) * BN;

    const int aRow = warp_m * 64 + (l & 7) + ((l >> 3) & 1) * 8;
    const int aHi  = (l >> 4) & 1;
    const int bRow = warp_n * 32 + ((l >> 4) & 1) * 8 + (l & 7);
    const int bHi  = (l >> 3) & 1;
    const int lsw  = l & 7;

    const uint32_t aLaneS[NSTAGES] = {
        sbase + 0 * STAGE_BYTES + (uint32_t)(aRow * 128),
        sbase + 1 * STAGE_BYTES + (uint32_t)(aRow * 128),
        sbase + 2 * STAGE_BYTES + (uint32_t)(aRow * 128)
    };
    const uint32_t bLaneS[NSTAGES] = {
        sbase + 0 * STAGE_BYTES + A_STAGE_BYTES + (uint32_t)(bRow * 128),
        sbase + 1 * STAGE_BYTES + A_STAGE_BYTES + (uint32_t)(bRow * 128),
        sbase + 2 * STAGE_BYTES + A_STAGE_BYTES + (uint32_t)(bRow * 128)
    };

    float acc[4][4][4];
    #pragma unroll
    for (int mt = 0; mt < 4; mt++)
        #pragma unroll
        for (int nt = 0; nt < 4; nt++)
            #pragma unroll
            for (int r = 0; r < 4; r++) acc[mt][nt][r] = 0.f;

    load_stage(sbase + 0 * STAGE_BYTES, 0, rowBase, colBase, tid);
    CP_COMMIT();
    load_stage(sbase + 1 * STAGE_BYTES, 1, rowBase, colBase, tid);
    CP_COMMIT();

    int kt = 0;

    #define GEMM_ITER(STG)                                                        \
    do {                                                                          \
        CP_WAIT(1);                                                               \
        __syncthreads();                                                          \
        if (kt + 2 < KTILES) {                                                    \
            load_stage(sbase + (((STG) + 2) % NSTAGES) * STAGE_BYTES, kt + 2,     \
                       rowBase, colBase, tid);                                    \
        }                                                                         \
        CP_COMMIT();                                                              \
        {                                                                         \
            const uint32_t aLane = aLaneS[(STG)];                                 \
            const uint32_t bLane = bLaneS[(STG)];                                 \
            _Pragma("unroll")                                                     \
            for (int ks = 0; ks < 4; ks++) {                                      \
                int a[4][4], b[4][2];                                             \
                const uint32_t aChunk = (uint32_t)(((ks * 2 + aHi) ^ lsw) << 4);  \
                const uint32_t bChunk = (uint32_t)(((ks * 2 + bHi) ^ lsw) << 4);  \
                _Pragma("unroll")                                                 \
                for (int mt = 0; mt < 4; mt++) {                                  \
                    LDSM4(a[mt][0], a[mt][1], a[mt][2], a[mt][3],                 \
                          aLane + (uint32_t)(mt * 2048) + aChunk);                \
                }                                                                 \
                _Pragma("unroll")                                                 \
                for (int p = 0; p < 2; p++) {                                     \
                    LDSM4(b[2 * p][0], b[2 * p][1], b[2 * p + 1][0],              \
                          b[2 * p + 1][1],                                        \
                          bLane + (uint32_t)(p * 2048) + bChunk);                 \
                }                                                                 \
                _Pragma("unroll")                                                 \
                for (int mt = 0; mt < 4; mt++)                                    \
                    _Pragma("unroll")                                             \
                    for (int nt = 0; nt < 4; nt++)                                \
                        mma_f16(acc[mt][nt], a[mt], b[nt]);                       \
            }                                                                     \
        }                                                                         \
        kt++;                                                                     \
    } while (0)

    #pragma unroll 1
    for (int grp = 0; grp < KTILES / NSTAGES; grp++) {   // 21 groups of 3
        GEMM_ITER(0);
        GEMM_ITER(1);
        GEMM_ITER(2);
    }
    GEMM_ITER(0);   // kt = 63

    #undef GEMM_ITER

    const float gscale = g_alpha * (1.0f / 127.0f);
    #pragma unroll
    for (int mt = 0; mt < 4; mt++) {
        const int m0 = rowBase + warp_m * 64 + mt * 16 + (l >> 2);
        const float s0 = g_gamma[m0] * gscale;
        const float s1 = g_gamma[m0 + 8] * gscale;
        #pragma unroll
        for (int nt = 0; nt < 4; nt++) {
            const int cbase = colBase + warp_n * 32 + nt * 8 + ((l & 3) << 1);
            float2 o0, o1;
            o0.x = acc[mt][nt][0] * s0;
            o0.y = acc[mt][nt][1] * s0;
            o1.x = acc[mt][nt][2] * s1;
            o1.y = acc[mt][nt][3] * s1;
            *(float2*)(out + (size_t)m0 * N_DIM + cbase) = o0;
            *(float2*)(out + (size_t)(m0 + 8) * N_DIM + cbase) = o1;
        }
    }
}

// ---------------- launch: quant_w0 on L2-warm HIGH rows, gemm0 on those tiles ----------------
extern "C" void kernel_launch(void* const* d_in, const int* in_sizes, int n_in,
                              void* d_out, int out_size) {
    const float4* x4 = (const float4*)d_in[0];
    const float4* w4 = (const float4*)d_in[1];
    float* out = (float*)d_out;

    static bool init_done = false;
    static cudaStream_t s2;
    static cudaEvent_t evStart, evX, evW0, evW;
    if (!init_done) {
        cudaFuncSetAttribute(k_gemm_mma, cudaFuncAttributeMaxDynamicSharedMemorySize,
                             SMEM_TOTAL);
        cudaStreamCreateWithFlags(&s2, cudaStreamNonBlocking);
        cudaEventCreateWithFlags(&evStart, cudaEventDisableTiming);
        cudaEventCreateWithFlags(&evX, cudaEventDisableTiming);
        cudaEventCreateWithFlags(&evW0, cudaEventDisableTiming);
        cudaEventCreateWithFlags(&evW, cudaEventDisableTiming);
        init_done = true;
    }

    const int C0start = (N_DIM - W_ROWS0) * KP;   // high-row chunk (L2-warm tail)
    const int C0 = W_ROWS0 * KP;
    const int CR = C0start;                        // low rows [0, C0start)

    // fork: s2 quantizes x while main reduces |W|
    cudaEventRecord(evStart, 0);
    cudaStreamWaitEvent(s2, evStart, 0);
    k_quant_x<<<M_DIM, 256, 0, s2>>>(x4);
    cudaEventRecord(evX, s2);

    k_abs_partial<<<ABS_BLOCKS, 256>>>(w4);
    k_alpha_final<<<1, 256>>>();

    // quantize the HIGH W rows (read from warm L2), needed by gemm0
    k_quant_w<<<3648, 256>>>(w4, C0start, C0);
    cudaEventRecord(evW0, 0);

    // s2: low W rows quantize concurrently with gemm0
    cudaStreamWaitEvent(s2, evW0, 0);
    k_quant_w<<<4096, 256, 0, s2>>>(w4, 0, CR);
    cudaEventRecord(evW, s2);

    // gemm0: high 19 N-tiles (B data just written, L2-hot); 1216 CTAs = 4 waves
    cudaStreamWaitEvent(0, evX, 0);
    {
        dim3 grid0(NT0, M_DIM / BM);
        k_gemm_mma<<<grid0, 256, SMEM_TOTAL>>>(out, COL_OFF0);
    }

    // gemm rest: low 109 N-tiles
    cudaStreamWaitEvent(0, evW, 0);
    {
        dim3 grid1(N_TILES - NT0, M_DIM / BM);
        k_gemm_mma<<<grid1, 256, SMEM_TOTAL>>>(out, 0);
    }
}